// round 16
// baseline (speedup 1.0000x reference)
#include <cuda_runtime.h>
#include <cuda_bf16.h>
#include <cstdint>
#include <math.h>

// ---------------- problem constants ----------------
#define NB      2
#define LSEQ    2048
#define BL      4096          // NB*LSEQ
#define DMODEL  1024
#define DINNER  2048
#define DSTATE  16
#define DTRANK  64
#define XDBL_W  96            // DTRANK + 2*DSTATE
#define NCH     64            // scan chunks
#define CHUNK   32            // steps per chunk
#define XSPLIT  8             // x_proj split-K factor

// ---------------- scratch (static device globals; zero-init, no allocs) ----------------
__device__ float g_xz[(size_t)BL * 2 * DINNER];
__device__ float g_xconv[(size_t)BL * DINNER];
__device__ float g_xdbl[(size_t)BL * XDBL_W];
__device__ float g_delta[(size_t)BL * DINNER];     // also reused as out_proj split-K partials
__device__ float g_xpart[(size_t)XSPLIT * BL * XDBL_W];
__device__ float g_Hc[(size_t)NCH * NB * DINNER * DSTATE];
__device__ float g_Sc[(size_t)NCH * NB * DINNER];
__device__ float g_Hinit[(size_t)NCH * NB * DINNER * DSTATE];

__device__ __nv_bfloat16 g_hidden3[(size_t)BL * 3 * DMODEL];
__device__ __nv_bfloat16 g_Win3[(size_t)(2 * DINNER) * 3 * DMODEL];
__device__ __nv_bfloat16 g_xconv3[(size_t)BL * 3 * DINNER];
__device__ __nv_bfloat16 g_Wxproj3[(size_t)128 * 3 * DINNER];   // padded to 128 rows (zero)
__device__ __nv_bfloat16 g_dt3[(size_t)BL * 3 * DTRANK];
__device__ __nv_bfloat16 g_Wdt3[(size_t)DINNER * 3 * DTRANK];
__device__ __nv_bfloat16 g_y3[(size_t)BL * 3 * DINNER];
__device__ __nv_bfloat16 g_Wout3[(size_t)DMODEL * 3 * DINNER];

// ---------------- helpers ----------------
__device__ __forceinline__ float softplus_f(float x) {
    return (x > 20.f) ? x : log1pf(__expf(x));
}
__device__ __forceinline__ float silu_f(float x) {
    return x / (1.f + __expf(-x));
}
__device__ __forceinline__ uint32_t smem_u32(const void* p) {
    uint32_t a;
    asm("{ .reg .u64 t; cvta.to.shared.u64 t, %1; cvt.u32.u64 %0, t; }" : "=r"(a) : "l"(p));
    return a;
}

// cp.async
__device__ __forceinline__ void cp16(uint32_t dst, const void* src) {
    asm volatile("cp.async.cg.shared.global [%0], [%1], 16;" :: "r"(dst), "l"(src));
}
__device__ __forceinline__ void cp_commit() { asm volatile("cp.async.commit_group;"); }
template <int N> __device__ __forceinline__ void cp_wait() {
    asm volatile("cp.async.wait_group %0;" :: "n"(N));
}

// ldmatrix / mma
__device__ __forceinline__ void ldsm4(uint32_t& r0, uint32_t& r1, uint32_t& r2,
                                      uint32_t& r3, uint32_t addr) {
    asm volatile("ldmatrix.sync.aligned.m8n8.x4.shared.b16 {%0,%1,%2,%3}, [%4];"
                 : "=r"(r0), "=r"(r1), "=r"(r2), "=r"(r3) : "r"(addr));
}
__device__ __forceinline__ void mma16816(float* c, const uint32_t* a,
                                         const uint32_t* b) {
    asm volatile(
        "mma.sync.aligned.m16n8k16.row.col.f32.bf16.bf16.f32 "
        "{%0,%1,%2,%3}, {%4,%5,%6,%7}, {%8,%9}, {%0,%1,%2,%3};"
        : "+f"(c[0]), "+f"(c[1]), "+f"(c[2]), "+f"(c[3])
        : "r"(a[0]), "r"(a[1]), "r"(a[2]), "r"(a[3]), "r"(b[0]), "r"(b[1]));
}

// ---------------- HMMA NT GEMM: 128x128 tile, 4 warps (64x64), BK=32, 5-stage ----------------
// 2 CTAs/SM (100KB smem each). Grid = tile count.
#define BKB    32
#define RSTR   80
#define TILEB  (128 * RSTR)       // 10240 per operand
#define STAGEB (2 * TILEB)        // 20480
#define STAGES 5
#define GSMEM  (STAGES * STAGEB)  // 102400

template <int EPI>
__global__ __launch_bounds__(128, 2)
void gemm_hmma(const __nv_bfloat16* __restrict__ A,
               const __nv_bfloat16* __restrict__ B,
               float* __restrict__ C, int N, int Kp, int ldc,
               const float* __restrict__ bias, int kofs, int KT,
               size_t partStride, int tilesX, int tilesY, int tilesZ)
{
    extern __shared__ __align__(16) char smem[];
    const uint32_t sbase = smem_u32(smem);

    const int tid = threadIdx.x;
    const int wid = tid >> 5, lane = tid & 31;
    const int wm = wid >> 1, wn = wid & 1;          // 2 x 2 warp grid, 64x64 each
    const int lrow = tid >> 2, lseg = tid & 3;      // 32 rows x 4 segs
    const uint32_t soff = (uint32_t)lrow * RSTR + lseg * 16;
    const int q = lane >> 3, i8 = lane & 7;
    const int gid = lane >> 2, l4 = lane & 3;

    const int total = tilesX * tilesY * tilesZ;

    for (int tile = blockIdx.x; tile < total; tile += gridDim.x) {
        int tz = tile / (tilesX * tilesY);
        int rem = tile - tz * tilesX * tilesY;
        int ty = rem / tilesX;
        int tx = rem - ty * tilesX;
        const int bm = ty * 128, bn = tx * 128;
        const int kz = kofs + tz * KT;
        float* Cp = C + (size_t)tz * partStride;

        const __nv_bfloat16* Ag = A + (size_t)(bm + lrow) * Kp + (size_t)kz * BKB + lseg * 8;
        const __nv_bfloat16* Bg = B + (size_t)(bn + lrow) * Kp + (size_t)kz * BKB + lseg * 8;

        auto load_tile = [&](int kt, int stage) {
            uint32_t sA = sbase + stage * STAGEB;
            uint32_t sB = sA + TILEB;
            const __nv_bfloat16* a = Ag + (size_t)kt * BKB;
            const __nv_bfloat16* b = Bg + (size_t)kt * BKB;
#pragma unroll
            for (int i = 0; i < 4; i++)
                cp16(sA + soff + i * (32u * RSTR), a + (size_t)(32 * i) * Kp);
#pragma unroll
            for (int i = 0; i < 4; i++)
                cp16(sB + soff + i * (32u * RSTR), b + (size_t)(32 * i) * Kp);
        };

        float acc[4][8][4];
#pragma unroll
        for (int mt = 0; mt < 4; mt++)
#pragma unroll
            for (int nt = 0; nt < 8; nt++)
#pragma unroll
                for (int j = 0; j < 4; j++) acc[mt][nt][j] = 0.f;

        // protect smem stage reuse across tiles
        __syncthreads();

#pragma unroll
        for (int p = 0; p < STAGES - 1; p++) {
            load_tile(p, p);
            cp_commit();
        }

        int sc = 0;                  // compute stage (mod STAGES)
        int sl = STAGES - 1;         // next load stage (mod STAGES)
        for (int kt = 0; kt < KT; kt++) {
            cp_wait<STAGES - 2>();
            __syncthreads();

            const int ln = kt + STAGES - 1;
            if (ln < KT) {
                load_tile(ln, sl);
                sl = (sl + 1 == STAGES) ? 0 : sl + 1;
            }
            cp_commit();

            const uint32_t sA = sbase + sc * STAGEB;
            const uint32_t sB = sA + TILEB;
            sc = (sc + 1 == STAGES) ? 0 : sc + 1;

#pragma unroll
            for (int ks = 0; ks < 2; ks++) {
                uint32_t a[4][4];
#pragma unroll
                for (int mt = 0; mt < 4; mt++) {
                    int row = wm * 64 + mt * 16 + ((q & 1) << 3) + i8;
                    int kk = ks * 16 + ((q >> 1) << 3);
                    ldsm4(a[mt][0], a[mt][1], a[mt][2], a[mt][3],
                          sA + (uint32_t)row * RSTR + kk * 2);
                }
                uint32_t b[8][2];
#pragma unroll
                for (int p = 0; p < 4; p++) {
                    int n = wn * 64 + p * 16 + ((q >> 1) << 3) + i8;
                    int kk = ks * 16 + ((q & 1) << 3);
                    uint32_t r0, r1, r2, r3;
                    ldsm4(r0, r1, r2, r3, sB + (uint32_t)n * RSTR + kk * 2);
                    b[2 * p][0] = r0;     b[2 * p][1] = r1;
                    b[2 * p + 1][0] = r2; b[2 * p + 1][1] = r3;
                }
#pragma unroll
                for (int mt = 0; mt < 4; mt++)
#pragma unroll
                    for (int nt = 0; nt < 8; nt++)
                        mma16816(acc[mt][nt], a[mt], b[nt]);
            }
        }

        // epilogue
#pragma unroll
        for (int mt = 0; mt < 4; mt++) {
            const int row0 = bm + wm * 64 + mt * 16 + gid;
#pragma unroll
            for (int nt = 0; nt < 8; nt++) {
                const int col = bn + wn * 64 + nt * 8 + l4 * 2;
                if (col < N) {
                    float t0 = acc[mt][nt][0], t1 = acc[mt][nt][1];
                    float t2 = acc[mt][nt][2], t3 = acc[mt][nt][3];
                    if (EPI == 1) {
                        float b0 = bias[col], b1 = bias[col + 1];
                        t0 = softplus_f(t0 + b0); t1 = softplus_f(t1 + b1);
                        t2 = softplus_f(t2 + b0); t3 = softplus_f(t3 + b1);
                    }
                    *(float2*)(Cp + (size_t)row0 * ldc + col) = make_float2(t0, t1);
                    *(float2*)(Cp + (size_t)(row0 + 8) * ldc + col) = make_float2(t2, t3);
                }
            }
        }
    }
}

// ---------------- fp32 -> bf16 hi/lo triple conversion (device body) ----------------
// pat 0 (A-side): (h, l, h)   pat 1 (B-side): (h, h, l)
__device__ __forceinline__ void triple_emit(const float* __restrict__ X, int ldx,
                                            __nv_bfloat16* __restrict__ Y, int ldy,
                                            int CW8, int idx, int pat)
{
    int r = idx / CW8;
    int c8 = idx - r * CW8;
    const float* src = X + (size_t)r * ldx + c8 * 8;
    float4 x0 = *(const float4*)src;
    float4 x1 = *(const float4*)(src + 4);
    float xs[8] = {x0.x, x0.y, x0.z, x0.w, x1.x, x1.y, x1.z, x1.w};
    __align__(16) unsigned short v[24];
#pragma unroll
    for (int i = 0; i < 8; i++) {
        __nv_bfloat16 h = __float2bfloat16(xs[i]);
        float hf = __bfloat162float(h);
        __nv_bfloat16 l = __float2bfloat16(xs[i] - hf);
        unsigned short hu = *(unsigned short*)&h;
        unsigned short lu = *(unsigned short*)&l;
        if (pat == 0) { v[3 * i] = hu; v[3 * i + 1] = lu; v[3 * i + 2] = hu; }
        else          { v[3 * i] = hu; v[3 * i + 1] = hu; v[3 * i + 2] = lu; }
    }
    uint4* dst = (uint4*)(Y + (size_t)r * ldy + (size_t)c8 * 24);
    const uint4* pv = (const uint4*)v;
    dst[0] = pv[0]; dst[1] = pv[1]; dst[2] = pv[2];
}

// ALL input/weight conversions in one launch
__global__ __launch_bounds__(256)
void conv_all(const float* __restrict__ hidden, __nv_bfloat16* __restrict__ hidden3,
              const float* __restrict__ W_in, __nv_bfloat16* __restrict__ Win3,
              const float* __restrict__ W_out, __nv_bfloat16* __restrict__ Wout3,
              const float* __restrict__ W_xprj, __nv_bfloat16* __restrict__ Wxproj3,
              const float* __restrict__ W_dt, __nv_bfloat16* __restrict__ Wdt3)
{
    int bx = blockIdx.x;
    if (bx < 2048) {
        int idx = bx * 256 + threadIdx.x;
        triple_emit(hidden, DMODEL, hidden3, 3 * DMODEL, DMODEL / 8, idx, 0);
    } else if (bx < 4096) {
        int idx = (bx - 2048) * 256 + threadIdx.x;
        triple_emit(W_in, DMODEL, Win3, 3 * DMODEL, DMODEL / 8, idx, 1);
    } else if (bx < 5120) {
        int idx = (bx - 4096) * 256 + threadIdx.x;
        triple_emit(W_out, DINNER, Wout3, 3 * DINNER, DINNER / 8, idx, 1);
    } else if (bx < 5216) {
        int idx = (bx - 5120) * 256 + threadIdx.x;
        triple_emit(W_xprj, DINNER, Wxproj3, 3 * DINNER, DINNER / 8, idx, 1);
    } else {
        int idx = (bx - 5216) * 256 + threadIdx.x;
        triple_emit(W_dt, DTRANK, Wdt3, 3 * DTRANK, DTRANK / 8, idx, 1);
    }
}

// ---------------- depthwise causal conv1d + SiLU, fused triple output ----------------
__global__ __launch_bounds__(256)
void conv_silu_fused(const float* __restrict__ xz,
                     const float* __restrict__ cw,
                     const float* __restrict__ cb,
                     float* __restrict__ xconv,
                     __nv_bfloat16* __restrict__ xconv3)
{
    int idx = blockIdx.x * 256 + threadIdx.x;   // over (BL/4) * (DINNER/4)
    int d0 = (idx & 511) << 2;
    int rowc = idx >> 9;
    int row0 = rowc << 2;
    int t0 = row0 & (LSEQ - 1);

    float4 w[4];
#pragma unroll
    for (int i = 0; i < 4; i++) w[i] = *(const float4*)(cw + (d0 + i) * 4);
    float4 bias4 = *(const float4*)(cb + d0);
    float bb[4] = {bias4.x, bias4.y, bias4.z, bias4.w};

    float in[7][4];
#pragma unroll
    for (int j = 0; j < 7; j++) {
        int trow = t0 - 3 + j;
        if (trow >= 0) {
            float4 v = *(const float4*)(xz + (size_t)(row0 - 3 + j) * (2 * DINNER) + d0);
            in[j][0] = v.x; in[j][1] = v.y; in[j][2] = v.z; in[j][3] = v.w;
        } else {
            in[j][0] = in[j][1] = in[j][2] = in[j][3] = 0.f;
        }
    }

#pragma unroll
    for (int j = 0; j < 4; j++) {
        float s[4];
#pragma unroll
        for (int i = 0; i < 4; i++) {
            float a = bb[i];
            a = fmaf(in[j][i],     w[i].x, a);
            a = fmaf(in[j + 1][i], w[i].y, a);
            a = fmaf(in[j + 2][i], w[i].z, a);
            a = fmaf(in[j + 3][i], w[i].w, a);
            s[i] = silu_f(a);
        }
        size_t row = (size_t)(row0 + j);
        *(float4*)(xconv + row * DINNER + d0) = make_float4(s[0], s[1], s[2], s[3]);

        __align__(8) unsigned short v[12];
#pragma unroll
        for (int i = 0; i < 4; i++) {
            __nv_bfloat16 h = __float2bfloat16(s[i]);
            float hf = __bfloat162float(h);
            __nv_bfloat16 l = __float2bfloat16(s[i] - hf);
            v[3 * i]     = *(unsigned short*)&h;
            v[3 * i + 1] = *(unsigned short*)&l;
            v[3 * i + 2] = *(unsigned short*)&h;
        }
        uint2* dst = (uint2*)(xconv3 + row * (3 * DINNER) + (size_t)d0 * 3);
        const uint2* pv = (const uint2*)v;
        dst[0] = pv[0]; dst[1] = pv[1]; dst[2] = pv[2];
    }
}

// ---------------- split-K reduce (8-way) + fused dt3 triple emit ----------------
__global__ __launch_bounds__(256)
void reduce8_kernel(const float* __restrict__ part, float* __restrict__ xdbl,
                    __nv_bfloat16* __restrict__ dt3)
{
    int i = blockIdx.x * 256 + threadIdx.x;
    int row = i / 24, c4 = i - row * 24;
    const size_t n = (size_t)BL * XDBL_W;
    size_t off = (size_t)row * XDBL_W + c4 * 4;
    float4 s = *(const float4*)(part + off);
#pragma unroll
    for (int p = 1; p < XSPLIT; p++) {
        float4 v = *(const float4*)(part + (size_t)p * n + off);
        s.x += v.x; s.y += v.y; s.z += v.z; s.w += v.w;
    }
    *(float4*)(xdbl + off) = s;

    if (c4 < 16) {
        float xs[4] = {s.x, s.y, s.z, s.w};
        __align__(8) unsigned short v[12];
#pragma unroll
        for (int j = 0; j < 4; j++) {
            __nv_bfloat16 h = __float2bfloat16(xs[j]);
            float hf = __bfloat162float(h);
            __nv_bfloat16 l = __float2bfloat16(xs[j] - hf);
            unsigned short hu = *(unsigned short*)&h;
            unsigned short lu = *(unsigned short*)&l;
            v[3 * j] = hu; v[3 * j + 1] = lu; v[3 * j + 2] = hu;
        }
        uint2* dst = (uint2*)(dt3 + (size_t)row * (3 * DTRANK) + (size_t)c4 * 12);
        const uint2* pv = (const uint2*)v;
        dst[0] = pv[0]; dst[1] = pv[1]; dst[2] = pv[2];
    }
}

// ---------------- 2-way reduce for out_proj split-K ----------------
__global__ __launch_bounds__(256)
void reduce2_kernel(const float* __restrict__ part, float* __restrict__ outp)
{
    int i = blockIdx.x * 256 + threadIdx.x;       // over BL*DMODEL/4
    const size_t n = (size_t)BL * DMODEL;
    float4 a = *(const float4*)(part + (size_t)i * 4);
    float4 b = *(const float4*)(part + n + (size_t)i * 4);
    float4 r;
    r.x = a.x + b.x; r.y = a.y + b.y; r.z = a.z + b.z; r.w = a.w + b.w;
    *(float4*)(outp + (size_t)i * 4) = r;
}

// ---------------- chunked selective scan ----------------
__global__ __launch_bounds__(256)
void scan_pass1(const float* __restrict__ xconv,
                const float* __restrict__ xdbl,
                const float* __restrict__ delta,
                const float* __restrict__ A_log,
                float* __restrict__ Hc, float* __restrict__ Sc)
{
    int d = blockIdx.x * 64 + (threadIdx.x >> 2);
    int n4 = threadIdx.x & 3;
    int b = blockIdx.y, c = blockIdx.z;

    float4 Al = *(const float4*)(A_log + d * DSTATE + n4 * 4);
    float A0 = -__expf(Al.x), A1 = -__expf(Al.y);
    float A2 = -__expf(Al.z), A3 = -__expf(Al.w);

    float h0 = 0.f, h1 = 0.f, h2 = 0.f, h3 = 0.f, S = 0.f;
    size_t row0 = (size_t)b * LSEQ + (size_t)c * CHUNK;
    const float* dp = delta + row0 * DINNER + d;
    const float* up = xconv + row0 * DINNER + d;
    const float* bp = xdbl + row0 * XDBL_W + DTRANK + n4 * 4;

#pragma unroll 4
    for (int i = 0; i < CHUNK; i++) {
        float dl = dp[(size_t)i * DINNER];
        float u  = up[(size_t)i * DINNER];
        float4 Bt = *(const float4*)(bp + (size_t)i * XDBL_W);
        float du = dl * u;
        h0 = fmaf(__expf(dl * A0), h0, du * Bt.x);
        h1 = fmaf(__expf(dl * A1), h1, du * Bt.y);
        h2 = fmaf(__expf(dl * A2), h2, du * Bt.z);
        h3 = fmaf(__expf(dl * A3), h3, du * Bt.w);
        S += dl;
    }
    size_t o = ((size_t)c * NB + b) * DINNER + d;
    *(float4*)(Hc + o * DSTATE + n4 * 4) = make_float4(h0, h1, h2, h3);
    if (n4 == 0) Sc[o] = S;
}

__global__ __launch_bounds__(256)
void scan_mid(const float* __restrict__ Hc, const float* __restrict__ Sc,
              const float* __restrict__ A_log, float* __restrict__ Hinit)
{
    int tid = blockIdx.x * 256 + threadIdx.x;
    int n4 = tid & 3;
    int d = (tid >> 2) & (DINNER - 1);
    int b = tid >> 13;

    float4 Al = *(const float4*)(A_log + d * DSTATE + n4 * 4);
    float A0 = -__expf(Al.x), A1 = -__expf(Al.y);
    float A2 = -__expf(Al.z), A3 = -__expf(Al.w);

    float c0 = 0.f, c1 = 0.f, c2 = 0.f, c3 = 0.f;
#pragma unroll
    for (int c = 0; c < NCH; c++) {
        size_t o = ((size_t)c * NB + b) * DINNER + d;
        *(float4*)(Hinit + o * DSTATE + n4 * 4) = make_float4(c0, c1, c2, c3);
        float S = Sc[o];
        float4 H = *(const float4*)(Hc + o * DSTATE + n4 * 4);
        c0 = fmaf(__expf(A0 * S), c0, H.x);
        c1 = fmaf(__expf(A1 * S), c1, H.y);
        c2 = fmaf(__expf(A2 * S), c2, H.z);
        c3 = fmaf(__expf(A3 * S), c3, H.w);
    }
}

__global__ __launch_bounds__(256)
void scan_pass2(const float* __restrict__ xz,
                const float* __restrict__ xconv,
                const float* __restrict__ xdbl,
                const float* __restrict__ delta,
                const float* __restrict__ A_log,
                const float* __restrict__ D_skip,
                const float* __restrict__ Hinit,
                __nv_bfloat16* __restrict__ y3)
{
    int d = blockIdx.x * 64 + (threadIdx.x >> 2);
    int n4 = threadIdx.x & 3;
    int b = blockIdx.y, c = blockIdx.z;

    float4 Al = *(const float4*)(A_log + d * DSTATE + n4 * 4);
    float A0 = -__expf(Al.x), A1 = -__expf(Al.y);
    float A2 = -__expf(Al.z), A3 = -__expf(Al.w);
    float Dv = D_skip[d];

    size_t o = ((size_t)c * NB + b) * DINNER + d;
    float4 h4 = *(const float4*)(Hinit + o * DSTATE + n4 * 4);
    float h0 = h4.x, h1 = h4.y, h2 = h4.z, h3 = h4.w;

    size_t row0 = (size_t)b * LSEQ + (size_t)c * CHUNK;
    const float* dp = delta + row0 * DINNER + d;
    const float* up = xconv + row0 * DINNER + d;
    const float* bp = xdbl + row0 * XDBL_W + DTRANK + n4 * 4;
    const float* cp = bp + DSTATE;
    const float* zp = xz + row0 * (2 * DINNER) + DINNER + d;
    __nv_bfloat16* yo = y3 + row0 * (3 * DINNER) + 3 * d;

#pragma unroll 2
    for (int i = 0; i < CHUNK; i++) {
        float dl = dp[(size_t)i * DINNER];
        float u  = up[(size_t)i * DINNER];
        float4 Bt = *(const float4*)(bp + (size_t)i * XDBL_W);
        float4 Ct = *(const float4*)(cp + (size_t)i * XDBL_W);
        float du = dl * u;
        h0 = fmaf(__expf(dl * A0), h0, du * Bt.x);
        h1 = fmaf(__expf(dl * A1), h1, du * Bt.y);
        h2 = fmaf(__expf(dl * A2), h2, du * Bt.z);
        h3 = fmaf(__expf(dl * A3), h3, du * Bt.w);
        float yp = h0 * Ct.x + h1 * Ct.y + h2 * Ct.z + h3 * Ct.w;
        yp += __shfl_xor_sync(0xffffffffu, yp, 1);
        yp += __shfl_xor_sync(0xffffffffu, yp, 2);
        if (n4 == 0) {
            float z = zp[(size_t)i * (2 * DINNER)];
            float yv = (yp + u * Dv) * silu_f(z);
            __nv_bfloat16 h = __float2bfloat16(yv);
            float hf = __bfloat162float(h);
            __nv_bfloat16 l = __float2bfloat16(yv - hf);
            __nv_bfloat16* op = yo + (size_t)i * (3 * DINNER);
            op[0] = h; op[1] = l; op[2] = h;
        }
    }
}

// ---------------- launch ----------------
extern "C" void kernel_launch(void* const* d_in, const int* in_sizes, int n_in,
                              void* d_out, int out_size)
{
    (void)in_sizes; (void)n_in; (void)out_size;
    const float* hidden = (const float*)d_in[0];
    const float* W_in   = (const float*)d_in[1];
    const float* conv_w = (const float*)d_in[2];
    const float* conv_b = (const float*)d_in[3];
    const float* W_xprj = (const float*)d_in[4];
    const float* W_dt   = (const float*)d_in[5];
    const float* b_dt   = (const float*)d_in[6];
    const float* A_log  = (const float*)d_in[7];
    const float* D_skip = (const float*)d_in[8];
    const float* W_out  = (const float*)d_in[9];
    float* out = (float*)d_out;

    float *xz, *xconv, *xdbl, *delta, *xpart, *Hc, *Sc, *Hinit;
    cudaGetSymbolAddress((void**)&xz,    g_xz);
    cudaGetSymbolAddress((void**)&xconv, g_xconv);
    cudaGetSymbolAddress((void**)&xdbl,  g_xdbl);
    cudaGetSymbolAddress((void**)&delta, g_delta);
    cudaGetSymbolAddress((void**)&xpart, g_xpart);
    cudaGetSymbolAddress((void**)&Hc,    g_Hc);
    cudaGetSymbolAddress((void**)&Sc,    g_Sc);
    cudaGetSymbolAddress((void**)&Hinit, g_Hinit);
    __nv_bfloat16 *hidden3, *Win3, *xconv3, *Wxproj3, *dt3, *Wdt3, *y3, *Wout3;
    cudaGetSymbolAddress((void**)&hidden3, g_hidden3);
    cudaGetSymbolAddress((void**)&Win3,    g_Win3);
    cudaGetSymbolAddress((void**)&xconv3,  g_xconv3);
    cudaGetSymbolAddress((void**)&Wxproj3, g_Wxproj3);
    cudaGetSymbolAddress((void**)&dt3,     g_dt3);
    cudaGetSymbolAddress((void**)&Wdt3,    g_Wdt3);
    cudaGetSymbolAddress((void**)&y3,      g_y3);
    cudaGetSymbolAddress((void**)&Wout3,   g_Wout3);

    cudaFuncSetAttribute(gemm_hmma<0>, cudaFuncAttributeMaxDynamicSharedMemorySize, GSMEM);
    cudaFuncSetAttribute(gemm_hmma<1>, cudaFuncAttributeMaxDynamicSharedMemorySize, GSMEM);

    // 1) all conversions in one launch
    conv_all<<<5280, 256>>>(hidden, hidden3, W_in, Win3, W_out, Wout3,
                            W_xprj, Wxproj3, W_dt, Wdt3);

    // 2) in_proj: 1024 tiles (32x32), one tile per CTA
    gemm_hmma<0><<<1024, 128, GSMEM>>>(hidden3, Win3, xz, 2 * DINNER, 3 * DMODEL, 2 * DINNER,
                                       nullptr, 0, 96, 0, 32, 32, 1);

    // 3) depthwise causal conv + silu + fused triple emit
    conv_silu_fused<<<(BL / 4) * (DINNER / 4) / 256, 256>>>(xz, conv_w, conv_b, xconv, xconv3);

    // 4) x_proj split-K: 256 tiles (1 x 32 x 8), 24 chunks per slice
    gemm_hmma<0><<<256, 128, GSMEM>>>(xconv3, Wxproj3, xpart, XDBL_W, 3 * DINNER, XDBL_W,
                                      nullptr, 0, 192 / XSPLIT, (size_t)BL * XDBL_W, 1, 32, XSPLIT);

    // 5) reduce + fused dt3 triple emit
    reduce8_kernel<<<(BL * XDBL_W / 4) / 256, 256>>>(xpart, xdbl, dt3);

    // 6) delta = softplus(dt @ W_dt^T + b_dt): 512 tiles (16x32), one per CTA
    gemm_hmma<1><<<512, 128, GSMEM>>>(dt3, Wdt3, delta, DINNER, 3 * DTRANK, DINNER,
                                      b_dt, 0, 6, 0, 16, 32, 1);

    // 7-9) chunked selective scan (NCH=64); pass2 emits y3 directly
    scan_pass1<<<dim3(DINNER / 64, NB, NCH), 256>>>(xconv, xdbl, delta, A_log, Hc, Sc);
    scan_mid<<<(NB * DINNER * 4) / 256, 256>>>(Hc, Sc, A_log, Hinit);
    scan_pass2<<<dim3(DINNER / 64, NB, NCH), 256>>>(xz, xconv, xdbl, delta, A_log, D_skip, Hinit, y3);

    // 10) out_proj split-K x2: 512 tiles (8 x 32 x 2), KT=96 per slice.
    //     g_delta is dead after scan_pass2; reuse it for the two 16MB partials.
    gemm_hmma<0><<<512, 128, GSMEM>>>(y3, Wout3, delta, DMODEL, 3 * DINNER, DMODEL,
                                      nullptr, 0, 96, (size_t)BL * DMODEL, 8, 32, 2);

    // 11) sum the two partials into the output
    reduce2_kernel<<<(BL * DMODEL / 4) / 256, 256>>>(delta, out);
}

// round 17
// speedup vs baseline: 1.0214x; 1.0214x over previous
#include <cuda_runtime.h>
#include <cuda_bf16.h>
#include <cstdint>
#include <math.h>

// ---------------- problem constants ----------------
#define NB      2
#define LSEQ    2048
#define BL      4096          // NB*LSEQ
#define DMODEL  1024
#define DINNER  2048
#define DSTATE  16
#define DTRANK  64
#define XDBL_W  96            // DTRANK + 2*DSTATE
#define NCH     64            // scan chunks
#define CHUNK   32            // steps per chunk
#define XSPLIT  8             // x_proj split-K factor

// ---------------- scratch (static device globals; zero-init, no allocs) ----------------
__device__ float g_xz[(size_t)BL * 2 * DINNER];
__device__ float g_xconv[(size_t)BL * DINNER];
__device__ float g_xdbl[(size_t)BL * XDBL_W];
__device__ float g_delta[(size_t)BL * DINNER];
__device__ float g_xpart[(size_t)XSPLIT * BL * XDBL_W];
__device__ float g_Hc[(size_t)NCH * NB * DINNER * DSTATE];
__device__ float g_Sc[(size_t)NCH * NB * DINNER];
__device__ float g_Hinit[(size_t)NCH * NB * DINNER * DSTATE];

__device__ __nv_bfloat16 g_hidden3[(size_t)BL * 3 * DMODEL];
__device__ __nv_bfloat16 g_Win3[(size_t)(2 * DINNER) * 3 * DMODEL];
__device__ __nv_bfloat16 g_xconv3[(size_t)BL * 3 * DINNER];
__device__ __nv_bfloat16 g_Wxproj3[(size_t)128 * 3 * DINNER];   // padded to 128 rows (zero)
__device__ __nv_bfloat16 g_dt3[(size_t)BL * 3 * DTRANK];
__device__ __nv_bfloat16 g_Wdt3[(size_t)DINNER * 3 * DTRANK];
__device__ __nv_bfloat16 g_y3[(size_t)BL * 3 * DINNER];
__device__ __nv_bfloat16 g_Wout3[(size_t)DMODEL * 3 * DINNER];

// ---------------- helpers ----------------
__device__ __forceinline__ float softplus_f(float x) {
    return (x > 20.f) ? x : log1pf(__expf(x));
}
__device__ __forceinline__ float silu_f(float x) {
    return x / (1.f + __expf(-x));
}
__device__ __forceinline__ uint32_t smem_u32(const void* p) {
    uint32_t a;
    asm("{ .reg .u64 t; cvta.to.shared.u64 t, %1; cvt.u32.u64 %0, t; }" : "=r"(a) : "l"(p));
    return a;
}

// cp.async
__device__ __forceinline__ void cp16(uint32_t dst, const void* src) {
    asm volatile("cp.async.cg.shared.global [%0], [%1], 16;" :: "r"(dst), "l"(src));
}
__device__ __forceinline__ void cp_commit() { asm volatile("cp.async.commit_group;"); }
template <int N> __device__ __forceinline__ void cp_wait() {
    asm volatile("cp.async.wait_group %0;" :: "n"(N));
}

// ldmatrix / mma
__device__ __forceinline__ void ldsm4(uint32_t& r0, uint32_t& r1, uint32_t& r2,
                                      uint32_t& r3, uint32_t addr) {
    asm volatile("ldmatrix.sync.aligned.m8n8.x4.shared.b16 {%0,%1,%2,%3}, [%4];"
                 : "=r"(r0), "=r"(r1), "=r"(r2), "=r"(r3) : "r"(addr));
}
__device__ __forceinline__ void mma16816(float* c, const uint32_t* a,
                                         const uint32_t* b) {
    asm volatile(
        "mma.sync.aligned.m16n8k16.row.col.f32.bf16.bf16.f32 "
        "{%0,%1,%2,%3}, {%4,%5,%6,%7}, {%8,%9}, {%0,%1,%2,%3};"
        : "+f"(c[0]), "+f"(c[1]), "+f"(c[2]), "+f"(c[3])
        : "r"(a[0]), "r"(a[1]), "r"(a[2]), "r"(a[3]), "r"(b[0]), "r"(b[1]));
}

// ---------------- HMMA NT GEMM: 128x128 tile, 4 warps (64x64), BK=32, 5-stage ----------------
// 2 CTAs/SM (100KB smem each). Grid = tile count for big GEMMs.
#define BKB    32
#define RSTR   80
#define TILEB  (128 * RSTR)       // 10240 per operand
#define STAGEB (2 * TILEB)        // 20480
#define STAGES 5
#define GSMEM  (STAGES * STAGEB)  // 102400

template <int EPI>
__global__ __launch_bounds__(128, 2)
void gemm_hmma(const __nv_bfloat16* __restrict__ A,
               const __nv_bfloat16* __restrict__ B,
               float* __restrict__ C, int N, int Kp, int ldc,
               const float* __restrict__ bias, int kofs, int KT,
               size_t partStride, int tilesX, int tilesY, int tilesZ)
{
    extern __shared__ __align__(16) char smem[];
    const uint32_t sbase = smem_u32(smem);

    const int tid = threadIdx.x;
    const int wid = tid >> 5, lane = tid & 31;
    const int wm = wid >> 1, wn = wid & 1;          // 2 x 2 warp grid, 64x64 each
    const int lrow = tid >> 2, lseg = tid & 3;      // 32 rows x 4 segs
    const uint32_t soff = (uint32_t)lrow * RSTR + lseg * 16;
    const int q = lane >> 3, i8 = lane & 7;
    const int gid = lane >> 2, l4 = lane & 3;

    const int total = tilesX * tilesY * tilesZ;

    for (int tile = blockIdx.x; tile < total; tile += gridDim.x) {
        int tz = tile / (tilesX * tilesY);
        int rem = tile - tz * tilesX * tilesY;
        int ty = rem / tilesX;
        int tx = rem - ty * tilesX;
        const int bm = ty * 128, bn = tx * 128;
        const int kz = kofs + tz * KT;
        float* Cp = C + (size_t)tz * partStride;

        const __nv_bfloat16* Ag = A + (size_t)(bm + lrow) * Kp + (size_t)kz * BKB + lseg * 8;
        const __nv_bfloat16* Bg = B + (size_t)(bn + lrow) * Kp + (size_t)kz * BKB + lseg * 8;

        auto load_tile = [&](int kt, int stage) {
            uint32_t sA = sbase + stage * STAGEB;
            uint32_t sB = sA + TILEB;
            const __nv_bfloat16* a = Ag + (size_t)kt * BKB;
            const __nv_bfloat16* b = Bg + (size_t)kt * BKB;
#pragma unroll
            for (int i = 0; i < 4; i++)
                cp16(sA + soff + i * (32u * RSTR), a + (size_t)(32 * i) * Kp);
#pragma unroll
            for (int i = 0; i < 4; i++)
                cp16(sB + soff + i * (32u * RSTR), b + (size_t)(32 * i) * Kp);
        };

        float acc[4][8][4];
#pragma unroll
        for (int mt = 0; mt < 4; mt++)
#pragma unroll
            for (int nt = 0; nt < 8; nt++)
#pragma unroll
                for (int j = 0; j < 4; j++) acc[mt][nt][j] = 0.f;

        // protect smem stage reuse across tiles
        __syncthreads();

#pragma unroll
        for (int p = 0; p < STAGES - 1; p++) {
            load_tile(p, p);
            cp_commit();
        }

        int sc = 0;                  // compute stage (mod STAGES)
        int sl = STAGES - 1;         // next load stage (mod STAGES)
        for (int kt = 0; kt < KT; kt++) {
            cp_wait<STAGES - 2>();
            __syncthreads();

            const int ln = kt + STAGES - 1;
            if (ln < KT) {
                load_tile(ln, sl);
                sl = (sl + 1 == STAGES) ? 0 : sl + 1;
            }
            cp_commit();

            const uint32_t sA = sbase + sc * STAGEB;
            const uint32_t sB = sA + TILEB;
            sc = (sc + 1 == STAGES) ? 0 : sc + 1;

#pragma unroll
            for (int ks = 0; ks < 2; ks++) {
                uint32_t a[4][4];
#pragma unroll
                for (int mt = 0; mt < 4; mt++) {
                    int row = wm * 64 + mt * 16 + ((q & 1) << 3) + i8;
                    int kk = ks * 16 + ((q >> 1) << 3);
                    ldsm4(a[mt][0], a[mt][1], a[mt][2], a[mt][3],
                          sA + (uint32_t)row * RSTR + kk * 2);
                }
                uint32_t b[8][2];
#pragma unroll
                for (int p = 0; p < 4; p++) {
                    int n = wn * 64 + p * 16 + ((q >> 1) << 3) + i8;
                    int kk = ks * 16 + ((q & 1) << 3);
                    uint32_t r0, r1, r2, r3;
                    ldsm4(r0, r1, r2, r3, sB + (uint32_t)n * RSTR + kk * 2);
                    b[2 * p][0] = r0;     b[2 * p][1] = r1;
                    b[2 * p + 1][0] = r2; b[2 * p + 1][1] = r3;
                }
#pragma unroll
                for (int mt = 0; mt < 4; mt++)
#pragma unroll
                    for (int nt = 0; nt < 8; nt++)
                        mma16816(acc[mt][nt], a[mt], b[nt]);
            }
        }

        // epilogue
#pragma unroll
        for (int mt = 0; mt < 4; mt++) {
            const int row0 = bm + wm * 64 + mt * 16 + gid;
#pragma unroll
            for (int nt = 0; nt < 8; nt++) {
                const int col = bn + wn * 64 + nt * 8 + l4 * 2;
                if (col < N) {
                    float t0 = acc[mt][nt][0], t1 = acc[mt][nt][1];
                    float t2 = acc[mt][nt][2], t3 = acc[mt][nt][3];
                    if (EPI == 1) {
                        float b0 = bias[col], b1 = bias[col + 1];
                        t0 = softplus_f(t0 + b0); t1 = softplus_f(t1 + b1);
                        t2 = softplus_f(t2 + b0); t3 = softplus_f(t3 + b1);
                    }
                    *(float2*)(Cp + (size_t)row0 * ldc + col) = make_float2(t0, t1);
                    *(float2*)(Cp + (size_t)(row0 + 8) * ldc + col) = make_float2(t2, t3);
                }
            }
        }
    }
}

// ---------------- fp32 -> bf16 hi/lo triple conversion (device body) ----------------
// pat 0 (A-side): (h, l, h)   pat 1 (B-side): (h, h, l)
__device__ __forceinline__ void triple_emit(const float* __restrict__ X, int ldx,
                                            __nv_bfloat16* __restrict__ Y, int ldy,
                                            int CW8, int idx, int pat)
{
    int r = idx / CW8;
    int c8 = idx - r * CW8;
    const float* src = X + (size_t)r * ldx + c8 * 8;
    float4 x0 = *(const float4*)src;
    float4 x1 = *(const float4*)(src + 4);
    float xs[8] = {x0.x, x0.y, x0.z, x0.w, x1.x, x1.y, x1.z, x1.w};
    __align__(16) unsigned short v[24];
#pragma unroll
    for (int i = 0; i < 8; i++) {
        __nv_bfloat16 h = __float2bfloat16(xs[i]);
        float hf = __bfloat162float(h);
        __nv_bfloat16 l = __float2bfloat16(xs[i] - hf);
        unsigned short hu = *(unsigned short*)&h;
        unsigned short lu = *(unsigned short*)&l;
        if (pat == 0) { v[3 * i] = hu; v[3 * i + 1] = lu; v[3 * i + 2] = hu; }
        else          { v[3 * i] = hu; v[3 * i + 1] = hu; v[3 * i + 2] = lu; }
    }
    uint4* dst = (uint4*)(Y + (size_t)r * ldy + (size_t)c8 * 24);
    const uint4* pv = (const uint4*)v;
    dst[0] = pv[0]; dst[1] = pv[1]; dst[2] = pv[2];
}

// ALL input/weight conversions in one launch
__global__ __launch_bounds__(256)
void conv_all(const float* __restrict__ hidden, __nv_bfloat16* __restrict__ hidden3,
              const float* __restrict__ W_in, __nv_bfloat16* __restrict__ Win3,
              const float* __restrict__ W_out, __nv_bfloat16* __restrict__ Wout3,
              const float* __restrict__ W_xprj, __nv_bfloat16* __restrict__ Wxproj3,
              const float* __restrict__ W_dt, __nv_bfloat16* __restrict__ Wdt3)
{
    int bx = blockIdx.x;
    if (bx < 2048) {
        int idx = bx * 256 + threadIdx.x;
        triple_emit(hidden, DMODEL, hidden3, 3 * DMODEL, DMODEL / 8, idx, 0);
    } else if (bx < 4096) {
        int idx = (bx - 2048) * 256 + threadIdx.x;
        triple_emit(W_in, DMODEL, Win3, 3 * DMODEL, DMODEL / 8, idx, 1);
    } else if (bx < 5120) {
        int idx = (bx - 4096) * 256 + threadIdx.x;
        triple_emit(W_out, DINNER, Wout3, 3 * DINNER, DINNER / 8, idx, 1);
    } else if (bx < 5216) {
        int idx = (bx - 5120) * 256 + threadIdx.x;
        triple_emit(W_xprj, DINNER, Wxproj3, 3 * DINNER, DINNER / 8, idx, 1);
    } else {
        int idx = (bx - 5216) * 256 + threadIdx.x;
        triple_emit(W_dt, DTRANK, Wdt3, 3 * DTRANK, DTRANK / 8, idx, 1);
    }
}

// ---------------- depthwise causal conv1d + SiLU, fused triple output ----------------
__global__ __launch_bounds__(256)
void conv_silu_fused(const float* __restrict__ xz,
                     const float* __restrict__ cw,
                     const float* __restrict__ cb,
                     float* __restrict__ xconv,
                     __nv_bfloat16* __restrict__ xconv3)
{
    int idx = blockIdx.x * 256 + threadIdx.x;   // over (BL/4) * (DINNER/4)
    int d0 = (idx & 511) << 2;
    int rowc = idx >> 9;
    int row0 = rowc << 2;
    int t0 = row0 & (LSEQ - 1);

    float4 w[4];
#pragma unroll
    for (int i = 0; i < 4; i++) w[i] = *(const float4*)(cw + (d0 + i) * 4);
    float4 bias4 = *(const float4*)(cb + d0);
    float bb[4] = {bias4.x, bias4.y, bias4.z, bias4.w};

    float in[7][4];
#pragma unroll
    for (int j = 0; j < 7; j++) {
        int trow = t0 - 3 + j;
        if (trow >= 0) {
            float4 v = *(const float4*)(xz + (size_t)(row0 - 3 + j) * (2 * DINNER) + d0);
            in[j][0] = v.x; in[j][1] = v.y; in[j][2] = v.z; in[j][3] = v.w;
        } else {
            in[j][0] = in[j][1] = in[j][2] = in[j][3] = 0.f;
        }
    }

#pragma unroll
    for (int j = 0; j < 4; j++) {
        float s[4];
#pragma unroll
        for (int i = 0; i < 4; i++) {
            float a = bb[i];
            a = fmaf(in[j][i],     w[i].x, a);
            a = fmaf(in[j + 1][i], w[i].y, a);
            a = fmaf(in[j + 2][i], w[i].z, a);
            a = fmaf(in[j + 3][i], w[i].w, a);
            s[i] = silu_f(a);
        }
        size_t row = (size_t)(row0 + j);
        *(float4*)(xconv + row * DINNER + d0) = make_float4(s[0], s[1], s[2], s[3]);

        __align__(8) unsigned short v[12];
#pragma unroll
        for (int i = 0; i < 4; i++) {
            __nv_bfloat16 h = __float2bfloat16(s[i]);
            float hf = __bfloat162float(h);
            __nv_bfloat16 l = __float2bfloat16(s[i] - hf);
            v[3 * i]     = *(unsigned short*)&h;
            v[3 * i + 1] = *(unsigned short*)&l;
            v[3 * i + 2] = *(unsigned short*)&h;
        }
        uint2* dst = (uint2*)(xconv3 + row * (3 * DINNER) + (size_t)d0 * 3);
        const uint2* pv = (const uint2*)v;
        dst[0] = pv[0]; dst[1] = pv[1]; dst[2] = pv[2];
    }
}

// ---------------- split-K reduce (8-way) + fused dt3 triple emit ----------------
__global__ __launch_bounds__(256)
void reduce8_kernel(const float* __restrict__ part, float* __restrict__ xdbl,
                    __nv_bfloat16* __restrict__ dt3)
{
    int i = blockIdx.x * 256 + threadIdx.x;
    int row = i / 24, c4 = i - row * 24;
    const size_t n = (size_t)BL * XDBL_W;
    size_t off = (size_t)row * XDBL_W + c4 * 4;
    float4 s = *(const float4*)(part + off);
#pragma unroll
    for (int p = 1; p < XSPLIT; p++) {
        float4 v = *(const float4*)(part + (size_t)p * n + off);
        s.x += v.x; s.y += v.y; s.z += v.z; s.w += v.w;
    }
    *(float4*)(xdbl + off) = s;

    if (c4 < 16) {
        float xs[4] = {s.x, s.y, s.z, s.w};
        __align__(8) unsigned short v[12];
#pragma unroll
        for (int j = 0; j < 4; j++) {
            __nv_bfloat16 h = __float2bfloat16(xs[j]);
            float hf = __bfloat162float(h);
            __nv_bfloat16 l = __float2bfloat16(xs[j] - hf);
            unsigned short hu = *(unsigned short*)&h;
            unsigned short lu = *(unsigned short*)&l;
            v[3 * j] = hu; v[3 * j + 1] = lu; v[3 * j + 2] = hu;
        }
        uint2* dst = (uint2*)(dt3 + (size_t)row * (3 * DTRANK) + (size_t)c4 * 12);
        const uint2* pv = (const uint2*)v;
        dst[0] = pv[0]; dst[1] = pv[1]; dst[2] = pv[2];
    }
}

// ---------------- chunked selective scan ----------------
__global__ __launch_bounds__(256)
void scan_pass1(const float* __restrict__ xconv,
                const float* __restrict__ xdbl,
                const float* __restrict__ delta,
                const float* __restrict__ A_log,
                float* __restrict__ Hc, float* __restrict__ Sc)
{
    int d = blockIdx.x * 64 + (threadIdx.x >> 2);
    int n4 = threadIdx.x & 3;
    int b = blockIdx.y, c = blockIdx.z;

    float4 Al = *(const float4*)(A_log + d * DSTATE + n4 * 4);
    float A0 = -__expf(Al.x), A1 = -__expf(Al.y);
    float A2 = -__expf(Al.z), A3 = -__expf(Al.w);

    float h0 = 0.f, h1 = 0.f, h2 = 0.f, h3 = 0.f, S = 0.f;
    size_t row0 = (size_t)b * LSEQ + (size_t)c * CHUNK;
    const float* dp = delta + row0 * DINNER + d;
    const float* up = xconv + row0 * DINNER + d;
    const float* bp = xdbl + row0 * XDBL_W + DTRANK + n4 * 4;

#pragma unroll 4
    for (int i = 0; i < CHUNK; i++) {
        float dl = dp[(size_t)i * DINNER];
        float u  = up[(size_t)i * DINNER];
        float4 Bt = *(const float4*)(bp + (size_t)i * XDBL_W);
        float du = dl * u;
        h0 = fmaf(__expf(dl * A0), h0, du * Bt.x);
        h1 = fmaf(__expf(dl * A1), h1, du * Bt.y);
        h2 = fmaf(__expf(dl * A2), h2, du * Bt.z);
        h3 = fmaf(__expf(dl * A3), h3, du * Bt.w);
        S += dl;
    }
    size_t o = ((size_t)c * NB + b) * DINNER + d;
    *(float4*)(Hc + o * DSTATE + n4 * 4) = make_float4(h0, h1, h2, h3);
    if (n4 == 0) Sc[o] = S;
}

__global__ __launch_bounds__(256)
void scan_mid(const float* __restrict__ Hc, const float* __restrict__ Sc,
              const float* __restrict__ A_log, float* __restrict__ Hinit)
{
    int tid = blockIdx.x * 256 + threadIdx.x;
    int n4 = tid & 3;
    int d = (tid >> 2) & (DINNER - 1);
    int b = tid >> 13;

    float4 Al = *(const float4*)(A_log + d * DSTATE + n4 * 4);
    float A0 = -__expf(Al.x), A1 = -__expf(Al.y);
    float A2 = -__expf(Al.z), A3 = -__expf(Al.w);

    float c0 = 0.f, c1 = 0.f, c2 = 0.f, c3 = 0.f;
#pragma unroll
    for (int c = 0; c < NCH; c++) {
        size_t o = ((size_t)c * NB + b) * DINNER + d;
        *(float4*)(Hinit + o * DSTATE + n4 * 4) = make_float4(c0, c1, c2, c3);
        float S = Sc[o];
        float4 H = *(const float4*)(Hc + o * DSTATE + n4 * 4);
        c0 = fmaf(__expf(A0 * S), c0, H.x);
        c1 = fmaf(__expf(A1 * S), c1, H.y);
        c2 = fmaf(__expf(A2 * S), c2, H.z);
        c3 = fmaf(__expf(A3 * S), c3, H.w);
    }
}

__global__ __launch_bounds__(256)
void scan_pass2(const float* __restrict__ xz,
                const float* __restrict__ xconv,
                const float* __restrict__ xdbl,
                const float* __restrict__ delta,
                const float* __restrict__ A_log,
                const float* __restrict__ D_skip,
                const float* __restrict__ Hinit,
                __nv_bfloat16* __restrict__ y3)
{
    int d = blockIdx.x * 64 + (threadIdx.x >> 2);
    int n4 = threadIdx.x & 3;
    int b = blockIdx.y, c = blockIdx.z;

    float4 Al = *(const float4*)(A_log + d * DSTATE + n4 * 4);
    float A0 = -__expf(Al.x), A1 = -__expf(Al.y);
    float A2 = -__expf(Al.z), A3 = -__expf(Al.w);
    float Dv = D_skip[d];

    size_t o = ((size_t)c * NB + b) * DINNER + d;
    float4 h4 = *(const float4*)(Hinit + o * DSTATE + n4 * 4);
    float h0 = h4.x, h1 = h4.y, h2 = h4.z, h3 = h4.w;

    size_t row0 = (size_t)b * LSEQ + (size_t)c * CHUNK;
    const float* dp = delta + row0 * DINNER + d;
    const float* up = xconv + row0 * DINNER + d;
    const float* bp = xdbl + row0 * XDBL_W + DTRANK + n4 * 4;
    const float* cp = bp + DSTATE;
    const float* zp = xz + row0 * (2 * DINNER) + DINNER + d;
    __nv_bfloat16* yo = y3 + row0 * (3 * DINNER) + 3 * d;

#pragma unroll 2
    for (int i = 0; i < CHUNK; i++) {
        float dl = dp[(size_t)i * DINNER];
        float u  = up[(size_t)i * DINNER];
        float4 Bt = *(const float4*)(bp + (size_t)i * XDBL_W);
        float4 Ct = *(const float4*)(cp + (size_t)i * XDBL_W);
        float du = dl * u;
        h0 = fmaf(__expf(dl * A0), h0, du * Bt.x);
        h1 = fmaf(__expf(dl * A1), h1, du * Bt.y);
        h2 = fmaf(__expf(dl * A2), h2, du * Bt.z);
        h3 = fmaf(__expf(dl * A3), h3, du * Bt.w);
        float yp = h0 * Ct.x + h1 * Ct.y + h2 * Ct.z + h3 * Ct.w;
        yp += __shfl_xor_sync(0xffffffffu, yp, 1);
        yp += __shfl_xor_sync(0xffffffffu, yp, 2);
        if (n4 == 0) {
            float z = zp[(size_t)i * (2 * DINNER)];
            float yv = (yp + u * Dv) * silu_f(z);
            __nv_bfloat16 h = __float2bfloat16(yv);
            float hf = __bfloat162float(h);
            __nv_bfloat16 l = __float2bfloat16(yv - hf);
            __nv_bfloat16* op = yo + (size_t)i * (3 * DINNER);
            op[0] = h; op[1] = l; op[2] = h;
        }
    }
}

// ---------------- launch ----------------
extern "C" void kernel_launch(void* const* d_in, const int* in_sizes, int n_in,
                              void* d_out, int out_size)
{
    (void)in_sizes; (void)n_in; (void)out_size;
    const float* hidden = (const float*)d_in[0];
    const float* W_in   = (const float*)d_in[1];
    const float* conv_w = (const float*)d_in[2];
    const float* conv_b = (const float*)d_in[3];
    const float* W_xprj = (const float*)d_in[4];
    const float* W_dt   = (const float*)d_in[5];
    const float* b_dt   = (const float*)d_in[6];
    const float* A_log  = (const float*)d_in[7];
    const float* D_skip = (const float*)d_in[8];
    const float* W_out  = (const float*)d_in[9];
    float* out = (float*)d_out;

    float *xz, *xconv, *xdbl, *delta, *xpart, *Hc, *Sc, *Hinit;
    cudaGetSymbolAddress((void**)&xz,    g_xz);
    cudaGetSymbolAddress((void**)&xconv, g_xconv);
    cudaGetSymbolAddress((void**)&xdbl,  g_xdbl);
    cudaGetSymbolAddress((void**)&delta, g_delta);
    cudaGetSymbolAddress((void**)&xpart, g_xpart);
    cudaGetSymbolAddress((void**)&Hc,    g_Hc);
    cudaGetSymbolAddress((void**)&Sc,    g_Sc);
    cudaGetSymbolAddress((void**)&Hinit, g_Hinit);
    __nv_bfloat16 *hidden3, *Win3, *xconv3, *Wxproj3, *dt3, *Wdt3, *y3, *Wout3;
    cudaGetSymbolAddress((void**)&hidden3, g_hidden3);
    cudaGetSymbolAddress((void**)&Win3,    g_Win3);
    cudaGetSymbolAddress((void**)&xconv3,  g_xconv3);
    cudaGetSymbolAddress((void**)&Wxproj3, g_Wxproj3);
    cudaGetSymbolAddress((void**)&dt3,     g_dt3);
    cudaGetSymbolAddress((void**)&Wdt3,    g_Wdt3);
    cudaGetSymbolAddress((void**)&y3,      g_y3);
    cudaGetSymbolAddress((void**)&Wout3,   g_Wout3);

    cudaFuncSetAttribute(gemm_hmma<0>, cudaFuncAttributeMaxDynamicSharedMemorySize, GSMEM);
    cudaFuncSetAttribute(gemm_hmma<1>, cudaFuncAttributeMaxDynamicSharedMemorySize, GSMEM);

    // 1) all conversions in one launch
    conv_all<<<5280, 256>>>(hidden, hidden3, W_in, Win3, W_out, Wout3,
                            W_xprj, Wxproj3, W_dt, Wdt3);

    // 2) in_proj: 1024 tiles (32x32), one tile per CTA
    gemm_hmma<0><<<1024, 128, GSMEM>>>(hidden3, Win3, xz, 2 * DINNER, 3 * DMODEL, 2 * DINNER,
                                       nullptr, 0, 96, 0, 32, 32, 1);

    // 3) depthwise causal conv + silu + fused triple emit
    conv_silu_fused<<<(BL / 4) * (DINNER / 4) / 256, 256>>>(xz, conv_w, conv_b, xconv, xconv3);

    // 4) x_proj split-K: 256 tiles (1 x 32 x 8), 24 chunks per slice
    gemm_hmma<0><<<256, 128, GSMEM>>>(xconv3, Wxproj3, xpart, XDBL_W, 3 * DINNER, XDBL_W,
                                      nullptr, 0, 192 / XSPLIT, (size_t)BL * XDBL_W, 1, 32, XSPLIT);

    // 5) reduce + fused dt3 triple emit
    reduce8_kernel<<<(BL * XDBL_W / 4) / 256, 256>>>(xpart, xdbl, dt3);

    // 6) delta = softplus(dt @ W_dt^T + b_dt): 512 tiles (16x32), one per CTA
    gemm_hmma<1><<<512, 128, GSMEM>>>(dt3, Wdt3, delta, DINNER, 3 * DTRANK, DINNER,
                                      b_dt, 0, 6, 0, 16, 32, 1);

    // 7-9) chunked selective scan (NCH=64); pass2 emits y3 directly
    scan_pass1<<<dim3(DINNER / 64, NB, NCH), 256>>>(xconv, xdbl, delta, A_log, Hc, Sc);
    scan_mid<<<(NB * DINNER * 4) / 256, 256>>>(Hc, Sc, A_log, Hinit);
    scan_pass2<<<dim3(DINNER / 64, NB, NCH), 256>>>(xz, xconv, xdbl, delta, A_log, D_skip, Hinit, y3);

    // 10) out_proj: 256 tiles (8x32), single wave, full K per tile
    gemm_hmma<0><<<256, 128, GSMEM>>>(y3, Wout3, out, DMODEL, 3 * DINNER, DMODEL,
                                      nullptr, 0, 192, 0, 8, 32, 1);
}